// round 1
// baseline (speedup 1.0000x reference)
#include <cuda_runtime.h>

// ImageLinearAttention: B=4, C=128, H=W=128 (n=16384), HEADS=8, KD=VD=64.
//
// Pipeline:
//  K1: per (b, token-tile): k,v projections (per head) -> exp(scale*k) -> partial
//      ctx[d][e] = sum_t ek[d][t]*v[e][t] and partial S[d] = sum_t ek[d][t]
//  K2: reduce partials over tiles, ctx /= S, fold output proj:
//      M[b,h,d,o] = sum_e Wo[o, h*64+e] * ctx[b,h,d,e]
//  K3: per (b, token-tile): q projection -> exp -> per-token normalize ->
//      out[o][t] = sum_{h,d} M[b,h,d,o] * qsoft[h,d,t] + bo[o]
//
// No max-subtraction in softmax: values are tiny (|k| < ~1), mathematically
// identical to the reference softmax.

#define CC    128
#define NN    16384
#define NHH   8
#define K1B   64          // token-tile blocks per image (each does 2 tiles of 128)
#define QSCALE 0.35355339059327373f   // 64^-0.25

// scratch (allocation-free rule: __device__ globals)
__device__ float g_ctxp[4 * K1B * NHH * 64 * 64];   // ~33.5 MB partial ctx
__device__ float g_spart[4 * K1B * NHH * 64];       // partial softmax-k denominators
__device__ float g_M[4 * NHH * 64 * 128];           // folded ctx*Wo

extern __shared__ float smem[];

// ---------------------------------------------------------------------------
// K1: k/v projection + exp + ctx partial accumulation
// grid (K1B, 4), 256 threads, smem = xs(16384) + wk(8192) + wv(8192) + kt(64*129) + vt(64*129)
// ---------------------------------------------------------------------------
__global__ __launch_bounds__(256) void lin_attn_k1(
    const float* __restrict__ x,
    const float* __restrict__ Wk, const float* __restrict__ bk,
    const float* __restrict__ Wv, const float* __restrict__ bv)
{
    float* xs = smem;                  // [128][128]
    float* wk = xs + 16384;            // [64][128]
    float* wv = wk + 8192;             // [64][128]
    float* kt = wv + 8192;             // [64][129]  (pad 1: 2-way max conflict in GEMM)
    float* vt = kt + 64 * 129;         // [64][129]

    const int b   = blockIdx.y;
    const int blk = blockIdx.x;
    const int tid = threadIdx.x;
    const int dg  = tid >> 4;          // 0..15
    const int tg  = tid & 15;          // 0..15
    const int d0  = dg * 4;
    const int t0  = tg * 8;
    const int e0  = tg * 4;

    const float* xb = x + (size_t)b * CC * NN;

    for (int h = 0; h < NHH; h++) {
        // weights for this head (rows h*64 .. h*64+63 are contiguous)
        for (int i = tid; i < 8192; i += 256) {
            wk[i] = Wk[h * 8192 + i];
            wv[i] = Wv[h * 8192 + i];
        }
        float bkv[4], bvv[4];
        #pragma unroll
        for (int i = 0; i < 4; i++) {
            bkv[i] = bk[h * 64 + d0 + i];
            bvv[i] = bv[h * 64 + d0 + i];
        }
        float ctx[16];
        #pragma unroll
        for (int i = 0; i < 16; i++) ctx[i] = 0.f;
        float srow = 0.f;

        for (int tile = 0; tile < 2; tile++) {
            const int n0 = (blk * 2 + tile) * 128;
            __syncthreads();                       // prior phase done before xs/kt/vt reuse
            for (int i = tid; i < 16384; i += 256)
                xs[i] = xb[(i >> 7) * NN + n0 + (i & 127)];
            __syncthreads();

            // fused k+v projection: 4 d-rows x 8 tokens per thread
            float ak[4][8], av[4][8];
            #pragma unroll
            for (int i = 0; i < 4; i++)
                #pragma unroll
                for (int j = 0; j < 8; j++) { ak[i][j] = 0.f; av[i][j] = 0.f; }

            for (int c = 0; c < 128; c++) {
                float4 xa = *(const float4*)(xs + c * 128 + t0);
                float4 xc = *(const float4*)(xs + c * 128 + t0 + 4);
                float xv[8] = {xa.x, xa.y, xa.z, xa.w, xc.x, xc.y, xc.z, xc.w};
                #pragma unroll
                for (int i = 0; i < 4; i++) {
                    float wkv = wk[(d0 + i) * 128 + c];
                    float wvc = wv[(d0 + i) * 128 + c];
                    #pragma unroll
                    for (int j = 0; j < 8; j++) {
                        ak[i][j] = fmaf(wkv, xv[j], ak[i][j]);
                        av[i][j] = fmaf(wvc, xv[j], av[i][j]);
                    }
                }
            }
            #pragma unroll
            for (int i = 0; i < 4; i++)
                #pragma unroll
                for (int j = 0; j < 8; j++) {
                    kt[(d0 + i) * 129 + t0 + j] = __expf(QSCALE * (ak[i][j] + bkv[i]));
                    vt[(d0 + i) * 129 + t0 + j] = av[i][j] + bvv[i];
                }
            __syncthreads();

            // softmax-k denominator partials (threads 0..63 own one d each)
            if (tid < 64) {
                float s = 0.f;
                #pragma unroll 4
                for (int t = 0; t < 128; t++) s += kt[tid * 129 + t];
                srow += s;
            }

            // ctx partial: [64 d][64 e] += ek[64][128] * v[64][128]^T
            #pragma unroll 2
            for (int t = 0; t < 128; t++) {
                float kv[4], vv[4];
                #pragma unroll
                for (int i = 0; i < 4; i++) kv[i] = kt[(d0 + i) * 129 + t];
                #pragma unroll
                for (int j = 0; j < 4; j++) vv[j] = vt[(e0 + j) * 129 + t];
                #pragma unroll
                for (int i = 0; i < 4; i++)
                    #pragma unroll
                    for (int j = 0; j < 4; j++)
                        ctx[i * 4 + j] = fmaf(kv[i], vv[j], ctx[i * 4 + j]);
            }
            __syncthreads();
        }

        float* dst = g_ctxp + (((size_t)(b * K1B + blk) * NHH + h) << 12);
        #pragma unroll
        for (int i = 0; i < 4; i++) {
            float4 v4 = make_float4(ctx[i * 4 + 0], ctx[i * 4 + 1],
                                    ctx[i * 4 + 2], ctx[i * 4 + 3]);
            *(float4*)(dst + (d0 + i) * 64 + e0) = v4;
        }
        if (tid < 64) g_spart[((b * K1B + blk) * NHH + h) * 64 + tid] = srow;
        __syncthreads();
    }
}

// ---------------------------------------------------------------------------
// K2: reduce partials, normalize, fold Wo -> M[b,h,d,o]
// grid 32 (= b*8 + h), 256 threads
// ---------------------------------------------------------------------------
__global__ __launch_bounds__(256) void lin_attn_k2(const float* __restrict__ Wo)
{
    float* ctx_s = smem;               // [64][64]
    float* wo_s  = ctx_s + 4096;       // [e][o] transposed: [64][128]
    float* S_s   = wo_s + 8192;        // [64]

    const int bh = blockIdx.x;
    const int b  = bh >> 3;
    const int h  = bh & 7;
    const int tid = threadIdx.x;

    if (tid < 64) {
        float s = 0.f;
        for (int blk = 0; blk < K1B; blk++)
            s += g_spart[((b * K1B + blk) * NHH + h) * 64 + tid];
        S_s[tid] = 1.f / s;
    }

    // Wo slice, transposed to [e][o] for conflict-free reads below
    for (int idx = tid; idx < 8192; idx += 256) {
        int o = idx >> 6, e = idx & 63;
        wo_s[e * 128 + o] = Wo[o * 512 + h * 64 + e];
    }
    __syncthreads();

    const size_t base = ((size_t)(b * K1B) * NHH + h) << 12;   // blk stride = NHH*4096
    for (int idx = tid; idx < 4096; idx += 256) {
        float s = 0.f;
        const float* src = g_ctxp + base + idx;
        for (int blk = 0; blk < K1B; blk++) s += src[(size_t)blk * NHH * 4096];
        ctx_s[idx] = s * S_s[idx >> 6];
    }
    __syncthreads();

    // M[d][o] = sum_e Wo[o, h*64+e] * ctx[d][e]
    for (int idx = tid; idx < 8192; idx += 256) {
        int d = idx >> 7, o = idx & 127;
        float s = 0.f;
        #pragma unroll 4
        for (int e = 0; e < 64; e++)
            s = fmaf(wo_s[e * 128 + o], ctx_s[d * 64 + e], s);
        g_M[(((b * NHH) + h) * 64 + d) * 128 + o] = s;
    }
}

// ---------------------------------------------------------------------------
// K3: q projection + softmax + M application + bias
// grid (128, 4), 256 threads, smem = xs(16384) + wbuf(8192) + eq(8192)
// ---------------------------------------------------------------------------
__global__ __launch_bounds__(256) void lin_attn_k3(
    const float* __restrict__ x,
    const float* __restrict__ Wq, const float* __restrict__ bq,
    const float* __restrict__ bo, float* __restrict__ out)
{
    float* xs   = smem;                // [128][128]
    float* wbuf = xs + 16384;          // [64][128] (Wq slice, then M slice)
    float* eq   = wbuf + 8192;         // [64][128] (no pad: all accesses token-contiguous)

    const int b   = blockIdx.y;
    const int n0  = blockIdx.x * 128;
    const int tid = threadIdx.x;
    const int dg  = tid >> 4;
    const int tg  = tid & 15;
    const int d0  = dg * 4;
    const int t0  = tg * 8;
    const int og  = dg * 8;

    const float* xb = x + (size_t)b * CC * NN;
    for (int i = tid; i < 16384; i += 256)
        xs[i] = xb[(i >> 7) * NN + n0 + (i & 127)];

    float acc[8][8];
    #pragma unroll
    for (int i = 0; i < 8; i++)
        #pragma unroll
        for (int j = 0; j < 8; j++) acc[i][j] = 0.f;

    for (int h = 0; h < NHH; h++) {
        __syncthreads();               // xs ready (h=0) / prior gemm done reading wbuf,eq
        for (int i = tid; i < 8192; i += 256) wbuf[i] = Wq[h * 8192 + i];
        float bqv[4];
        #pragma unroll
        for (int i = 0; i < 4; i++) bqv[i] = bq[h * 64 + d0 + i];
        __syncthreads();

        // q projection
        float a[4][8];
        #pragma unroll
        for (int i = 0; i < 4; i++)
            #pragma unroll
            for (int j = 0; j < 8; j++) a[i][j] = 0.f;

        for (int c = 0; c < 128; c++) {
            float4 xa = *(const float4*)(xs + c * 128 + t0);
            float4 xc = *(const float4*)(xs + c * 128 + t0 + 4);
            float xv[8] = {xa.x, xa.y, xa.z, xa.w, xc.x, xc.y, xc.z, xc.w};
            #pragma unroll
            for (int i = 0; i < 4; i++) {
                float w = wbuf[(d0 + i) * 128 + c];
                #pragma unroll
                for (int j = 0; j < 8; j++)
                    a[i][j] = fmaf(w, xv[j], a[i][j]);
            }
        }
        #pragma unroll
        for (int i = 0; i < 4; i++)
            #pragma unroll
            for (int j = 0; j < 8; j++)
                eq[(d0 + i) * 128 + t0 + j] = __expf(QSCALE * (a[i][j] + bqv[i]));
        __syncthreads();

        // softmax over d (per token)
        if (tid < 128) {
            float s = 0.f;
            #pragma unroll 4
            for (int d = 0; d < 64; d++) s += eq[d * 128 + tid];
            float r = 1.f / s;
            #pragma unroll 4
            for (int d = 0; d < 64; d++) eq[d * 128 + tid] *= r;
        }
        __syncthreads();

        // swap in M[b,h] and accumulate out += M^T-applied q
        for (int i = tid; i < 8192; i += 256)
            wbuf[i] = g_M[(((size_t)b * NHH + h) << 13) + i];
        __syncthreads();

        for (int d = 0; d < 64; d++) {
            float4 m0 = *(const float4*)(wbuf + d * 128 + og);
            float4 m1 = *(const float4*)(wbuf + d * 128 + og + 4);
            float4 q0 = *(const float4*)(eq + d * 128 + t0);
            float4 q1 = *(const float4*)(eq + d * 128 + t0 + 4);
            float mv[8] = {m0.x, m0.y, m0.z, m0.w, m1.x, m1.y, m1.z, m1.w};
            float qv[8] = {q0.x, q0.y, q0.z, q0.w, q1.x, q1.y, q1.z, q1.w};
            #pragma unroll
            for (int i = 0; i < 8; i++)
                #pragma unroll
                for (int j = 0; j < 8; j++)
                    acc[i][j] = fmaf(mv[i], qv[j], acc[i][j]);
        }
    }

    float* ob = out + (size_t)b * CC * NN + n0;
    #pragma unroll
    for (int i = 0; i < 8; i++) {
        float bb = bo[og + i];
        float4 r0 = make_float4(acc[i][0] + bb, acc[i][1] + bb,
                                acc[i][2] + bb, acc[i][3] + bb);
        float4 r1 = make_float4(acc[i][4] + bb, acc[i][5] + bb,
                                acc[i][6] + bb, acc[i][7] + bb);
        *(float4*)(ob + (og + i) * NN + t0)     = r0;
        *(float4*)(ob + (og + i) * NN + t0 + 4) = r1;
    }
}

// ---------------------------------------------------------------------------

extern "C" void kernel_launch(void* const* d_in, const int* in_sizes, int n_in,
                              void* d_out, int out_size)
{
    const float* x  = (const float*)d_in[0];
    const float* Wq = (const float*)d_in[1];
    const float* bq = (const float*)d_in[2];
    const float* Wk = (const float*)d_in[3];
    const float* bk = (const float*)d_in[4];
    const float* Wv = (const float*)d_in[5];
    const float* bv = (const float*)d_in[6];
    const float* Wo = (const float*)d_in[7];
    const float* bo = (const float*)d_in[8];
    float* out = (float*)d_out;

    const int SM1 = (16384 + 8192 + 8192 + 2 * 64 * 129) * 4;  // 197120
    const int SM2 = (4096 + 8192 + 64) * 4;                     // 49408
    const int SM3 = (16384 + 8192 + 8192) * 4;                  // 131072

    cudaFuncSetAttribute(lin_attn_k1, cudaFuncAttributeMaxDynamicSharedMemorySize, SM1);
    cudaFuncSetAttribute(lin_attn_k2, cudaFuncAttributeMaxDynamicSharedMemorySize, SM2);
    cudaFuncSetAttribute(lin_attn_k3, cudaFuncAttributeMaxDynamicSharedMemorySize, SM3);

    lin_attn_k1<<<dim3(K1B, 4), 256, SM1>>>(x, Wk, bk, Wv, bv);
    lin_attn_k2<<<32, 256, SM2>>>(Wo);
    lin_attn_k3<<<dim3(128, 4), 256, SM3>>>(x, Wq, bq, bo, out);
}

// round 2
// speedup vs baseline: 1.5915x; 1.5915x over previous
#include <cuda_runtime.h>

// ImageLinearAttention: B=4, C=128, H=W=128 (n=16384), HEADS=8, KD=VD=64.
//
// Pipeline:
//  K1: per (b, token-tile): k,v projections (per head) -> exp(scale*k) -> partial
//      ctx[d][e] = sum_t ek[d][t]*v[e][t] and partial S[d] = sum_t ek[d][t]
//  K2: reduce partials over tiles, ctx /= S, fold output proj:
//      M[b,h,d,o] = sum_e Wo[o, h*64+e] * ctx[b,h,d,e]
//  K3: per (b, token-tile): q projection -> exp -> per-token normalize ->
//      out[o][t] = sum_{h,d} M[b,h,d,o] * qsoft[h,d,t] + bo[o]
//
// No max-subtraction in softmax: values are tiny (|k| < ~1), mathematically
// identical to the reference softmax.

#define CC    128
#define NN    16384
#define NHH   8
#define K1B   64          // token-tile blocks per image (each does 2 tiles of 128)
#define QSCALE 0.35355339059327373f   // 64^-0.25

// scratch (allocation-free rule: __device__ globals)
__device__ float g_ctxp[4 * K1B * NHH * 64 * 64];   // ~33.5 MB partial ctx
__device__ float g_spart[4 * K1B * NHH * 64];       // partial softmax-k denominators
__device__ float g_M[4 * NHH * 64 * 128];           // folded ctx*Wo

extern __shared__ float smem[];

// ---------------------------------------------------------------------------
// K1: k/v projection + exp + ctx partial accumulation
// grid (K1B, 4), 256 threads, smem = xs(16384) + wk(8192) + wv(8192) + kt(64*129) + vt(64*129)
// ---------------------------------------------------------------------------
__global__ __launch_bounds__(256) void lin_attn_k1(
    const float* __restrict__ x,
    const float* __restrict__ Wk, const float* __restrict__ bk,
    const float* __restrict__ Wv, const float* __restrict__ bv)
{
    float* xs = smem;                  // [128][128]
    float* wk = xs + 16384;            // [64][128]
    float* wv = wk + 8192;             // [64][128]
    float* kt = wv + 8192;             // [64][129]  (pad 1: 2-way max conflict in GEMM)
    float* vt = kt + 64 * 129;         // [64][129]

    const int b   = blockIdx.y;
    const int blk = blockIdx.x;
    const int tid = threadIdx.x;
    const int dg  = tid >> 4;          // 0..15
    const int tg  = tid & 15;          // 0..15
    const int d0  = dg * 4;
    const int t0  = tg * 8;
    const int e0  = tg * 4;

    const float* xb = x + (size_t)b * CC * NN;

    for (int h = 0; h < NHH; h++) {
        // weights for this head (rows h*64 .. h*64+63 are contiguous)
        for (int i = tid; i < 8192; i += 256) {
            wk[i] = Wk[h * 8192 + i];
            wv[i] = Wv[h * 8192 + i];
        }
        float bkv[4], bvv[4];
        #pragma unroll
        for (int i = 0; i < 4; i++) {
            bkv[i] = bk[h * 64 + d0 + i];
            bvv[i] = bv[h * 64 + d0 + i];
        }
        float ctx[16];
        #pragma unroll
        for (int i = 0; i < 16; i++) ctx[i] = 0.f;
        float srow = 0.f;

        for (int tile = 0; tile < 2; tile++) {
            const int n0 = (blk * 2 + tile) * 128;
            __syncthreads();                       // prior phase done before xs/kt/vt reuse
            for (int i = tid; i < 16384; i += 256)
                xs[i] = xb[(i >> 7) * NN + n0 + (i & 127)];
            __syncthreads();

            // fused k+v projection: 4 d-rows x 8 tokens per thread
            float ak[4][8], av[4][8];
            #pragma unroll
            for (int i = 0; i < 4; i++)
                #pragma unroll
                for (int j = 0; j < 8; j++) { ak[i][j] = 0.f; av[i][j] = 0.f; }

            for (int c = 0; c < 128; c++) {
                float4 xa = *(const float4*)(xs + c * 128 + t0);
                float4 xc = *(const float4*)(xs + c * 128 + t0 + 4);
                float xv[8] = {xa.x, xa.y, xa.z, xa.w, xc.x, xc.y, xc.z, xc.w};
                #pragma unroll
                for (int i = 0; i < 4; i++) {
                    float wkv = wk[(d0 + i) * 128 + c];
                    float wvc = wv[(d0 + i) * 128 + c];
                    #pragma unroll
                    for (int j = 0; j < 8; j++) {
                        ak[i][j] = fmaf(wkv, xv[j], ak[i][j]);
                        av[i][j] = fmaf(wvc, xv[j], av[i][j]);
                    }
                }
            }
            #pragma unroll
            for (int i = 0; i < 4; i++)
                #pragma unroll
                for (int j = 0; j < 8; j++) {
                    kt[(d0 + i) * 129 + t0 + j] = __expf(QSCALE * (ak[i][j] + bkv[i]));
                    vt[(d0 + i) * 129 + t0 + j] = av[i][j] + bvv[i];
                }
            __syncthreads();

            // softmax-k denominator partials (threads 0..63 own one d each)
            if (tid < 64) {
                float s = 0.f;
                #pragma unroll 4
                for (int t = 0; t < 128; t++) s += kt[tid * 129 + t];
                srow += s;
            }

            // ctx partial: [64 d][64 e] += ek[64][128] * v[64][128]^T
            #pragma unroll 2
            for (int t = 0; t < 128; t++) {
                float kv[4], vv[4];
                #pragma unroll
                for (int i = 0; i < 4; i++) kv[i] = kt[(d0 + i) * 129 + t];
                #pragma unroll
                for (int j = 0; j < 4; j++) vv[j] = vt[(e0 + j) * 129 + t];
                #pragma unroll
                for (int i = 0; i < 4; i++)
                    #pragma unroll
                    for (int j = 0; j < 4; j++)
                        ctx[i * 4 + j] = fmaf(kv[i], vv[j], ctx[i * 4 + j]);
            }
            __syncthreads();
        }

        float* dst = g_ctxp + (((size_t)(b * K1B + blk) * NHH + h) << 12);
        #pragma unroll
        for (int i = 0; i < 4; i++) {
            float4 v4 = make_float4(ctx[i * 4 + 0], ctx[i * 4 + 1],
                                    ctx[i * 4 + 2], ctx[i * 4 + 3]);
            *(float4*)(dst + (d0 + i) * 64 + e0) = v4;
        }
        if (tid < 64) g_spart[((b * K1B + blk) * NHH + h) * 64 + tid] = srow;
        __syncthreads();
    }
}

// ---------------------------------------------------------------------------
// K2: reduce partials, normalize, fold Wo -> M[b,h,d,o]
// grid 32 (= b*8 + h), 256 threads
// ---------------------------------------------------------------------------
__global__ __launch_bounds__(256) void lin_attn_k2(const float* __restrict__ Wo)
{
    float* ctx_s = smem;               // [64][64]
    float* wo_s  = ctx_s + 4096;       // [e][o] transposed: [64][128]
    float* S_s   = wo_s + 8192;        // [64]

    const int bh = blockIdx.x;
    const int b  = bh >> 3;
    const int h  = bh & 7;
    const int tid = threadIdx.x;

    if (tid < 64) {
        float s = 0.f;
        for (int blk = 0; blk < K1B; blk++)
            s += g_spart[((b * K1B + blk) * NHH + h) * 64 + tid];
        S_s[tid] = 1.f / s;
    }

    // Wo slice, transposed to [e][o] for conflict-free reads below
    for (int idx = tid; idx < 8192; idx += 256) {
        int o = idx >> 6, e = idx & 63;
        wo_s[e * 128 + o] = Wo[o * 512 + h * 64 + e];
    }
    __syncthreads();

    const size_t base = ((size_t)(b * K1B) * NHH + h) << 12;   // blk stride = NHH*4096
    for (int idx = tid; idx < 4096; idx += 256) {
        float s = 0.f;
        const float* src = g_ctxp + base + idx;
        for (int blk = 0; blk < K1B; blk++) s += src[(size_t)blk * NHH * 4096];
        ctx_s[idx] = s * S_s[idx >> 6];
    }
    __syncthreads();

    // M[d][o] = sum_e Wo[o, h*64+e] * ctx[d][e]
    for (int idx = tid; idx < 8192; idx += 256) {
        int d = idx >> 7, o = idx & 127;
        float s = 0.f;
        #pragma unroll 4
        for (int e = 0; e < 64; e++)
            s = fmaf(wo_s[e * 128 + o], ctx_s[d * 64 + e], s);
        g_M[(((b * NHH) + h) * 64 + d) * 128 + o] = s;
    }
}

// ---------------------------------------------------------------------------
// K3: q projection + softmax + M application + bias
// grid (128, 4), 256 threads, smem = xs(16384) + wbuf(8192) + eq(8192)
// ---------------------------------------------------------------------------
__global__ __launch_bounds__(256) void lin_attn_k3(
    const float* __restrict__ x,
    const float* __restrict__ Wq, const float* __restrict__ bq,
    const float* __restrict__ bo, float* __restrict__ out)
{
    float* xs   = smem;                // [128][128]
    float* wbuf = xs + 16384;          // [64][128] (Wq slice, then M slice)
    float* eq   = wbuf + 8192;         // [64][128] (no pad: all accesses token-contiguous)

    const int b   = blockIdx.y;
    const int n0  = blockIdx.x * 128;
    const int tid = threadIdx.x;
    const int dg  = tid >> 4;
    const int tg  = tid & 15;
    const int d0  = dg * 4;
    const int t0  = tg * 8;
    const int og  = dg * 8;

    const float* xb = x + (size_t)b * CC * NN;
    for (int i = tid; i < 16384; i += 256)
        xs[i] = xb[(i >> 7) * NN + n0 + (i & 127)];

    float acc[8][8];
    #pragma unroll
    for (int i = 0; i < 8; i++)
        #pragma unroll
        for (int j = 0; j < 8; j++) acc[i][j] = 0.f;

    for (int h = 0; h < NHH; h++) {
        __syncthreads();               // xs ready (h=0) / prior gemm done reading wbuf,eq
        for (int i = tid; i < 8192; i += 256) wbuf[i] = Wq[h * 8192 + i];
        float bqv[4];
        #pragma unroll
        for (int i = 0; i < 4; i++) bqv[i] = bq[h * 64 + d0 + i];
        __syncthreads();

        // q projection
        float a[4][8];
        #pragma unroll
        for (int i = 0; i < 4; i++)
            #pragma unroll
            for (int j = 0; j < 8; j++) a[i][j] = 0.f;

        for (int c = 0; c < 128; c++) {
            float4 xa = *(const float4*)(xs + c * 128 + t0);
            float4 xc = *(const float4*)(xs + c * 128 + t0 + 4);
            float xv[8] = {xa.x, xa.y, xa.z, xa.w, xc.x, xc.y, xc.z, xc.w};
            #pragma unroll
            for (int i = 0; i < 4; i++) {
                float w = wbuf[(d0 + i) * 128 + c];
                #pragma unroll
                for (int j = 0; j < 8; j++)
                    a[i][j] = fmaf(w, xv[j], a[i][j]);
            }
        }
        #pragma unroll
        for (int i = 0; i < 4; i++)
            #pragma unroll
            for (int j = 0; j < 8; j++)
                eq[(d0 + i) * 128 + t0 + j] = __expf(QSCALE * (a[i][j] + bqv[i]));
        __syncthreads();

        // softmax over d (per token)
        if (tid < 128) {
            float s = 0.f;
            #pragma unroll 4
            for (int d = 0; d < 64; d++) s += eq[d * 128 + tid];
            float r = 1.f / s;
            #pragma unroll 4
            for (int d = 0; d < 64; d++) eq[d * 128 + tid] *= r;
        }
        __syncthreads();

        // swap in M[b,h] and accumulate out += M^T-applied q
        for (int i = tid; i < 8192; i += 256)
            wbuf[i] = g_M[(((size_t)b * NHH + h) << 13) + i];
        __syncthreads();

        for (int d = 0; d < 64; d++) {
            float4 m0 = *(const float4*)(wbuf + d * 128 + og);
            float4 m1 = *(const float4*)(wbuf + d * 128 + og + 4);
            float4 q0 = *(const float4*)(eq + d * 128 + t0);
            float4 q1 = *(const float4*)(eq + d * 128 + t0 + 4);
            float mv[8] = {m0.x, m0.y, m0.z, m0.w, m1.x, m1.y, m1.z, m1.w};
            float qv[8] = {q0.x, q0.y, q0.z, q0.w, q1.x, q1.y, q1.z, q1.w};
            #pragma unroll
            for (int i = 0; i < 8; i++)
                #pragma unroll
                for (int j = 0; j < 8; j++)
                    acc[i][j] = fmaf(mv[i], qv[j], acc[i][j]);
        }
    }

    float* ob = out + (size_t)b * CC * NN + n0;
    #pragma unroll
    for (int i = 0; i < 8; i++) {
        float bb = bo[og + i];
        float4 r0 = make_float4(acc[i][0] + bb, acc[i][1] + bb,
                                acc[i][2] + bb, acc[i][3] + bb);
        float4 r1 = make_float4(acc[i][4] + bb, acc[i][5] + bb,
                                acc[i][6] + bb, acc[i][7] + bb);
        *(float4*)(ob + (og + i) * NN + t0)     = r0;
        *(float4*)(ob + (og + i) * NN + t0 + 4) = r1;
    }
}

// ---------------------------------------------------------------------------

extern "C" void kernel_launch(void* const* d_in, const int* in_sizes, int n_in,
                              void* d_out, int out_size)
{
    const float* x  = (const float*)d_in[0];
    const float* Wq = (const float*)d_in[1];
    const float* bq = (const float*)d_in[2];
    const float* Wk = (const float*)d_in[3];
    const float* bk = (const float*)d_in[4];
    const float* Wv = (const float*)d_in[5];
    const float* bv = (const float*)d_in[6];
    const float* Wo = (const float*)d_in[7];
    const float* bo = (const float*)d_in[8];
    float* out = (float*)d_out;

    const int SM1 = (16384 + 8192 + 8192 + 2 * 64 * 129) * 4;  // 197120
    const int SM2 = (4096 + 8192 + 64) * 4;                     // 49408
    const int SM3 = (16384 + 8192 + 8192) * 4;                  // 131072

    cudaFuncSetAttribute(lin_attn_k1, cudaFuncAttributeMaxDynamicSharedMemorySize, SM1);
    cudaFuncSetAttribute(lin_attn_k2, cudaFuncAttributeMaxDynamicSharedMemorySize, SM2);
    cudaFuncSetAttribute(lin_attn_k3, cudaFuncAttributeMaxDynamicSharedMemorySize, SM3);

    lin_attn_k1<<<dim3(K1B, 4), 256, SM1>>>(x, Wk, bk, Wv, bv);
    lin_attn_k2<<<32, 256, SM2>>>(Wo);
    lin_attn_k3<<<dim3(128, 4), 256, SM3>>>(x, Wq, bq, bo, out);
}

// round 5
// speedup vs baseline: 3.7405x; 2.3503x over previous
#include <cuda_runtime.h>
#include <cuda_fp16.h>
#include <cstdint>

// ImageLinearAttention via warp-level mma.sync (m16n8k16 f16->f32).
// B=4, C=128, n=16384 (128 tiles x 128 tok), HEADS=8, KD=VD=64.
//
// P1: per (b,tile): k-proj -> exp -> ekT; v-proj (3-pass hi/lo) -> vT hi/lo;
//     ctx[d][e] partials (2-pass) + per-dim sum(ek) -> gmem.
// P2: reduce ctx over tiles, normalize by 1/S, fold Wo -> M (fp16 hi/lo).
// P3: recompute q -> exp -> qs fp16 -> per-(token,head) normalize in smem;
//     out = M*qs^T (2-pass hi/lo) + bo.

#define ROWB 136                      // halves per smem row (128 + 8 pad)
#define QSCALE 0.35355339059327373f   // 64^-0.25

__device__ float  g_ctxp[(size_t)512 * 8 * 64 * 64];  // [bt][head][d][e] partials
__device__ float  g_spart[512 * 512];                  // [bt][dim512] sum(ek) partials
__device__ __half g_Mh[4 * 4 * 128 * 128];             // [b][chunk][o][hd128] hi
__device__ __half g_Ml[4 * 4 * 128 * 128];             // lo

extern __shared__ char smraw[];

// ---------------- mma.sync helpers ----------------
__device__ __forceinline__ void mma16816(float c[4], const uint32_t a[4],
                                         const uint32_t b[2]) {
    asm volatile(
        "mma.sync.aligned.m16n8k16.row.col.f32.f16.f16.f32 "
        "{%0,%1,%2,%3}, {%4,%5,%6,%7}, {%8,%9}, {%0,%1,%2,%3};"
        : "+f"(c[0]), "+f"(c[1]), "+f"(c[2]), "+f"(c[3])
        : "r"(a[0]), "r"(a[1]), "r"(a[2]), "r"(a[3]), "r"(b[0]), "r"(b[1]));
}
// A fragment: 16x16 row-major at (r0, k0), row stride ROWB halves
__device__ __forceinline__ void ldA(uint32_t a[4], const __half* base, int r0, int k0) {
    const int lane = threadIdx.x & 31;
    const __half* p = base + (r0 + (lane >> 2)) * ROWB + k0 + ((lane & 3) << 1);
    a[0] = *(const uint32_t*)p;
    a[1] = *(const uint32_t*)(p + 8 * ROWB);
    a[2] = *(const uint32_t*)(p + 8);
    a[3] = *(const uint32_t*)(p + 8 * ROWB + 8);
}
// B fragment: 16(k)x8(n), stored [n][k] row-major (k contiguous)
__device__ __forceinline__ void ldB(uint32_t b[2], const __half* base, int n0, int k0) {
    const int lane = threadIdx.x & 31;
    const __half* p = base + (n0 + (lane >> 2)) * ROWB + k0 + ((lane & 3) << 1);
    b[0] = *(const uint32_t*)p;
    b[1] = *(const uint32_t*)(p + 8);
}
// 64x32 warp-tile GEMM over K=128: C[m-frag][n-frag][4] += A[wm..][k] * B[wn..][k]^T
__device__ __forceinline__ void gemm64x32(float C[4][4][4], const __half* A,
                                          const __half* B, int wm, int wn) {
    #pragma unroll
    for (int k0 = 0; k0 < 128; k0 += 16) {
        uint32_t a[4][4], b[4][2];
        #pragma unroll
        for (int i = 0; i < 4; i++) ldA(a[i], A, wm + 16 * i, k0);
        #pragma unroll
        for (int j = 0; j < 4; j++) ldB(b[j], B, wn + 8 * j, k0);
        #pragma unroll
        for (int i = 0; i < 4; i++)
            #pragma unroll
            for (int j = 0; j < 4; j++) mma16816(C[i][j], a[i], b[j]);
    }
}
__device__ __forceinline__ void zeroC(float C[4][4][4]) {
    #pragma unroll
    for (int i = 0; i < 4; i++)
        #pragma unroll
        for (int j = 0; j < 4; j++)
            #pragma unroll
            for (int q = 0; q < 4; q++) C[i][j][q] = 0.f;
}

// ---------------- P1 ----------------
#define SMEM1 (5 * 128 * ROWB * 2 + 1024 * 4)

__global__ __launch_bounds__(256, 1) void attn_p1(
    const float* __restrict__ x,
    const float* __restrict__ Wk, const float* __restrict__ bk,
    const float* __restrict__ Wv, const float* __restrict__ bv)
{
    __half* xh  = (__half*)smraw;
    __half* xl  = xh + 128 * ROWB;
    __half* wh  = xl + 128 * ROWB;   // W hi; later vT hi
    __half* wl  = wh + 128 * ROWB;   // W lo; later vT lo
    __half* ekT = wl + 128 * ROWB;
    float* sb_bk = (float*)(ekT + 128 * ROWB);
    float* sb_bv = sb_bk + 512;

    const int tid = threadIdx.x, w = tid >> 5, lane = tid & 31;
    const int tile = blockIdx.x, b = blockIdx.y;
    const int bt = b * 128 + tile;
    const float* xb = x + (size_t)b * 128 * 16384 + (size_t)tile * 128;

    for (int i = tid; i < 512; i += 256) { sb_bk[i] = bk[i]; sb_bv[i] = bv[i]; }

    // x tile -> fp16 hi/lo, layout [tok][ch]
    for (int idx = tid; idx < 16384; idx += 256) {
        int c = idx >> 7, t = idx & 127;
        float v = xb[(size_t)c * 16384 + t];
        __half h = __float2half_rn(v);
        xh[t * ROWB + c] = h;
        xl[t * ROWB + c] = __float2half_rn(v - __half2float(h));
    }
    __syncthreads();

    const int wm = (w >> 2) * 64, wn = (w & 3) * 32;

    for (int p = 0; p < 4; p++) {
        // ---- Wk chunk (hi only) ----
        for (int idx = tid; idx < 16384; idx += 256)
            wh[(idx >> 7) * ROWB + (idx & 127)] = __float2half_rn(Wk[p * 16384 + idx]);
        __syncthreads();

        float C[4][4][4];
        zeroC(C);
        gemm64x32(C, xh, wh, wm, wn);
        __syncthreads();                 // all warps done reading wh

        // K epilogue: ek = exp(scale*(val+bk)) -> ekT[dim][tok]
        #pragma unroll
        for (int i = 0; i < 4; i++)
            #pragma unroll
            for (int j = 0; j < 4; j++) {
                int tok = wm + 16 * i + (lane >> 2);
                int dim = wn + 8 * j + ((lane & 3) << 1);
                float b0 = sb_bk[p * 128 + dim], b1 = sb_bk[p * 128 + dim + 1];
                ekT[dim * ROWB + tok]           = __float2half_rn(__expf(QSCALE * (C[i][j][0] + b0)));
                ekT[(dim + 1) * ROWB + tok]     = __float2half_rn(__expf(QSCALE * (C[i][j][1] + b1)));
                ekT[dim * ROWB + tok + 8]       = __float2half_rn(__expf(QSCALE * (C[i][j][2] + b0)));
                ekT[(dim + 1) * ROWB + tok + 8] = __float2half_rn(__expf(QSCALE * (C[i][j][3] + b1)));
            }
        __syncthreads();

        // per-dim sum of rounded ek (softmax-k denominator partial)
        if (tid < 128) {
            float s = 0.f;
            #pragma unroll 8
            for (int t = 0; t < 128; t++) s += __half2float(ekT[tid * ROWB + t]);
            g_spart[(size_t)bt * 512 + p * 128 + tid] = s;
        }

        // ---- Wv chunk hi/lo ----
        for (int idx = tid; idx < 16384; idx += 256) {
            float v = Wv[p * 16384 + idx];
            __half h = __float2half_rn(v);
            int o = (idx >> 7) * ROWB + (idx & 127);
            wh[o] = h;
            wl[o] = __float2half_rn(v - __half2float(h));
        }
        __syncthreads();

        zeroC(C);
        gemm64x32(C, xh, wh, wm, wn);   // x_hi * W_hi
        gemm64x32(C, xh, wl, wm, wn);   // x_hi * W_lo
        gemm64x32(C, xl, wh, wm, wn);   // x_lo * W_hi
        __syncthreads();                 // all warps done reading wh/wl

        // V epilogue: v+bv, split hi/lo -> vT (overlays wh/wl), [dim][tok]
        #pragma unroll
        for (int i = 0; i < 4; i++)
            #pragma unroll
            for (int j = 0; j < 4; j++) {
                int tok = wm + 16 * i + (lane >> 2);
                int dim = wn + 8 * j + ((lane & 3) << 1);
                float bv0 = sb_bv[p * 128 + dim], bv1 = sb_bv[p * 128 + dim + 1];
                float v0 = C[i][j][0] + bv0, v1 = C[i][j][1] + bv1;
                float v2 = C[i][j][2] + bv0, v3 = C[i][j][3] + bv1;
                __half h0 = __float2half_rn(v0), h1 = __float2half_rn(v1);
                __half h2 = __float2half_rn(v2), h3 = __float2half_rn(v3);
                wh[dim * ROWB + tok]           = h0;
                wh[(dim + 1) * ROWB + tok]     = h1;
                wh[dim * ROWB + tok + 8]       = h2;
                wh[(dim + 1) * ROWB + tok + 8] = h3;
                wl[dim * ROWB + tok]           = __float2half_rn(v0 - __half2float(h0));
                wl[(dim + 1) * ROWB + tok]     = __float2half_rn(v1 - __half2float(h1));
                wl[dim * ROWB + tok + 8]       = __float2half_rn(v2 - __half2float(h2));
                wl[(dim + 1) * ROWB + tok + 8] = __float2half_rn(v3 - __half2float(h3));
            }
        __syncthreads();

        // ---- ctx GEMM: per head, D[d][e] = sum_t ekT[d][t] * vT[e][t] ----
        {
            const int hl = w >> 2, ww = w & 3;   // head-local, warp-in-head
            const int r0 = hl * 64 + ww * 16;
            float Cc[8][4];
            #pragma unroll
            for (int j = 0; j < 8; j++)
                #pragma unroll
                for (int q = 0; q < 4; q++) Cc[j][q] = 0.f;
            #pragma unroll
            for (int pass = 0; pass < 2; pass++) {
                const __half* V = pass ? wl : wh;
                #pragma unroll
                for (int k0 = 0; k0 < 128; k0 += 16) {
                    uint32_t a[4];
                    ldA(a, ekT, r0, k0);
                    #pragma unroll
                    for (int j = 0; j < 8; j++) {
                        uint32_t bb[2];
                        ldB(bb, V, hl * 64 + 8 * j, k0);
                        mma16816(Cc[j], a, bb);
                    }
                }
            }
            float* dst = g_ctxp + ((size_t)bt * 8 + 2 * p + hl) * 4096;
            const int d0 = ww * 16 + (lane >> 2);
            #pragma unroll
            for (int j = 0; j < 8; j++) {
                int e = 8 * j + ((lane & 3) << 1);
                *(float2*)(dst + d0 * 64 + e)       = make_float2(Cc[j][0], Cc[j][1]);
                *(float2*)(dst + (d0 + 8) * 64 + e) = make_float2(Cc[j][2], Cc[j][3]);
            }
        }
        __syncthreads();   // protect ekT / vT before next chunk reuses buffers
    }
}

// ---------------- P2: reduce + normalize + fold Wo ----------------
#define SMEM2 ((64 + 8192 + 64 * 65) * 4)

__global__ __launch_bounds__(256) void attn_p2(const float* __restrict__ Wo)
{
    float* rS    = (float*)smraw;        // [64]
    float* wo_s  = rS + 64;              // [o128][e64]
    float* ctx_s = wo_s + 8192;          // [d64][65]
    const int b = blockIdx.x >> 3, h = blockIdx.x & 7, tid = threadIdx.x;

    if (tid < 64) {
        float s = 0.f;
        for (int t = 0; t < 128; t++)
            s += g_spart[(size_t)(b * 128 + t) * 512 + h * 64 + tid];
        rS[tid] = 1.f / s;
    }
    for (int idx = tid; idx < 8192; idx += 256)
        wo_s[idx] = Wo[(idx >> 6) * 512 + h * 64 + (idx & 63)];
    __syncthreads();

    for (int idx = tid; idx < 4096; idx += 256) {
        int d = idx >> 6, e = idx & 63;
        const float* src = g_ctxp + (size_t)(b * 128) * 32768 + h * 4096 + idx;
        float s = 0.f;
        for (int t = 0; t < 128; t++) s += src[(size_t)t * 32768];
        ctx_s[d * 65 + e] = s * rS[d];
    }
    __syncthreads();

    const int p = h >> 1;
    const size_t mb = (size_t)(b * 4 + p) * 16384 + (h & 1) * 64;
    for (int idx = tid; idx < 8192; idx += 256) {
        int o = idx >> 6, d = idx & 63;
        float s = 0.f;
        #pragma unroll 8
        for (int e = 0; e < 64; e++)
            s = fmaf(wo_s[o * 64 + e], ctx_s[d * 65 + e], s);
        __half hi = __float2half_rn(s);
        g_Mh[mb + o * 128 + d] = hi;
        g_Ml[mb + o * 128 + d] = __float2half_rn(s - __half2float(hi));
    }
}

// ---------------- P3: q recompute + per-head softmax + M application ----------------
#define SMEM3 (5 * 128 * ROWB * 2 + (512 + 128) * 4)

__global__ __launch_bounds__(256, 1) void attn_p3(
    const float* __restrict__ x,
    const float* __restrict__ Wq, const float* __restrict__ bq,
    const float* __restrict__ bo, float* __restrict__ out)
{
    __half* xh   = (__half*)smraw;
    __half* wq   = xh + 128 * ROWB;
    __half* qs   = wq + 128 * ROWB;      // [tok][dim] fp16 (normalized in place)
    __half* Mh_s = qs + 128 * ROWB;      // [o][hd] fp16
    __half* Ml_s = Mh_s + 128 * ROWB;
    float* sb_bq = (float*)(Ml_s + 128 * ROWB);   // [512]
    float* sb_bo = sb_bq + 512;                    // [128]

    const int tid = threadIdx.x, w = tid >> 5, lane = tid & 31;
    const int tile = blockIdx.x, b = blockIdx.y;
    const float* xb = x + (size_t)b * 128 * 16384 + (size_t)tile * 128;

    for (int i = tid; i < 512; i += 256) sb_bq[i] = bq[i];
    if (tid < 128) sb_bo[tid] = bo[tid];

    for (int idx = tid; idx < 16384; idx += 256) {
        int c = idx >> 7, t = idx & 127;
        xh[t * ROWB + c] = __float2half_rn(xb[(size_t)c * 16384 + t]);
    }
    __syncthreads();

    const int wm = (w >> 2) * 64, wn = (w & 3) * 32;
    float Co[4][4][4];
    zeroC(Co);

    for (int p = 0; p < 4; p++) {
        for (int idx = tid; idx < 16384; idx += 256)
            wq[(idx >> 7) * ROWB + (idx & 127)] = __float2half_rn(Wq[p * 16384 + idx]);
        __syncthreads();

        float Cq[4][4][4];
        zeroC(Cq);
        gemm64x32(Cq, xh, wq, wm, wn);

        // q epilogue: eq = exp(scale*(val+bq)) -> qs[tok][dim]
        #pragma unroll
        for (int i = 0; i < 4; i++)
            #pragma unroll
            for (int j = 0; j < 4; j++) {
                int tok = wm + 16 * i + (lane >> 2);
                int dim = wn + 8 * j + ((lane & 3) << 1);
                float b0 = sb_bq[p * 128 + dim], b1 = sb_bq[p * 128 + dim + 1];
                __half2 h01 = __floats2half2_rn(__expf(QSCALE * (Cq[i][j][0] + b0)),
                                                __expf(QSCALE * (Cq[i][j][1] + b1)));
                __half2 h23 = __floats2half2_rn(__expf(QSCALE * (Cq[i][j][2] + b0)),
                                                __expf(QSCALE * (Cq[i][j][3] + b1)));
                *(__half2*)(qs + tok * ROWB + dim)       = h01;
                *(__half2*)(qs + (tok + 8) * ROWB + dim) = h23;
            }
        __syncthreads();

        // PER-HEAD softmax-q normalization in place.
        // Chunk p holds heads 2p (dims 0-63) and 2p+1 (dims 64-127).
        // 256 threads = (token, head-half): sum 64 rounded values, scale row.
        {
            const int tok = tid >> 1, hh = (tid & 1) << 6;
            __half* row = qs + tok * ROWB + hh;
            float s = 0.f;
            #pragma unroll
            for (int d = 0; d < 64; d += 2) {
                __half2 v = *(__half2*)(row + d);
                s += __low2float(v) + __high2float(v);
            }
            const float r = 1.f / s;
            #pragma unroll
            for (int d = 0; d < 64; d += 2) {
                __half2 v = *(__half2*)(row + d);
                *(__half2*)(row + d) =
                    __floats2half2_rn(__low2float(v) * r, __high2float(v) * r);
            }
        }
        __syncthreads();

        // load M chunk hi/lo
        {
            const uint32_t* gh = (const uint32_t*)(g_Mh + (size_t)(b * 4 + p) * 16384);
            const uint32_t* gl = (const uint32_t*)(g_Ml + (size_t)(b * 4 + p) * 16384);
            for (int idx = tid; idx < 8192; idx += 256) {
                int o = idx >> 6, k2 = (idx & 63) * 2;
                *(uint32_t*)(Mh_s + o * ROWB + k2) = gh[idx];
                *(uint32_t*)(Ml_s + o * ROWB + k2) = gl[idx];
            }
        }
        __syncthreads();

        // out GEMM: Co[o][t] += M[o][hd] * qn[t][hd]  (2-pass hi/lo)
        gemm64x32(Co, Mh_s, qs, wm, wn);
        gemm64x32(Co, Ml_s, qs, wm, wn);
        __syncthreads();
    }

    float* ob = out + (size_t)b * 128 * 16384 + (size_t)tile * 128;
    #pragma unroll
    for (int i = 0; i < 4; i++)
        #pragma unroll
        for (int j = 0; j < 4; j++) {
            int o = wm + 16 * i + (lane >> 2);
            int t = wn + 8 * j + ((lane & 3) << 1);
            float bo0 = sb_bo[o], bo8 = sb_bo[o + 8];
            *(float2*)(ob + (size_t)o * 16384 + t) =
                make_float2(Co[i][j][0] + bo0, Co[i][j][1] + bo0);
            *(float2*)(ob + (size_t)(o + 8) * 16384 + t) =
                make_float2(Co[i][j][2] + bo8, Co[i][j][3] + bo8);
        }
}

// ---------------------------------------------------------------------------
extern "C" void kernel_launch(void* const* d_in, const int* in_sizes, int n_in,
                              void* d_out, int out_size)
{
    const float* x  = (const float*)d_in[0];
    const float* Wq = (const float*)d_in[1];
    const float* bq = (const float*)d_in[2];
    const float* Wk = (const float*)d_in[3];
    const float* bk = (const float*)d_in[4];
    const float* Wv = (const float*)d_in[5];
    const float* bv = (const float*)d_in[6];
    const float* Wo = (const float*)d_in[7];
    const float* bo = (const float*)d_in[8];
    float* out = (float*)d_out;

    cudaFuncSetAttribute(attn_p1, cudaFuncAttributeMaxDynamicSharedMemorySize, SMEM1);
    cudaFuncSetAttribute(attn_p2, cudaFuncAttributeMaxDynamicSharedMemorySize, SMEM2);
    cudaFuncSetAttribute(attn_p3, cudaFuncAttributeMaxDynamicSharedMemorySize, SMEM3);

    attn_p1<<<dim3(128, 4), 256, SMEM1>>>(x, Wk, bk, Wv, bv);
    attn_p2<<<32, 256, SMEM2>>>(Wo);
    attn_p3<<<dim3(128, 4), 256, SMEM3>>>(x, Wq, bq, bo, out);
}

// round 6
// speedup vs baseline: 4.2285x; 1.1305x over previous
#include <cuda_runtime.h>
#include <cuda_fp16.h>
#include <cstdint>

// ImageLinearAttention via warp-level mma.sync (m16n8k16 f16->f32), ldmatrix
// fragment loads, 512-thread CTAs. B=4, C=128, n=16384, HEADS=8, KD=VD=64.
//
// P1: per (b,tile): k-proj -> exp -> ekT; v-proj (3-pass hi/lo) -> vT hi/lo;
//     ctx[d][e] partials (2-pass) + per-dim sum(ek) -> gmem.
// P2: reduce ctx over tiles, normalize by 1/S, fold Wo -> M (fp16 hi/lo).
// P3: recompute q -> exp -> per-(token,head) softmax normalize in smem;
//     out = M*qn^T (2-pass hi/lo) + bo.

#define ROWB 136                      // halves per smem row (128 + 8 pad)
#define QSCALE 0.35355339059327373f   // 64^-0.25

__device__ float  g_ctxp[(size_t)512 * 8 * 64 * 64];  // [bt][head][d][e] partials
__device__ float  g_spart[512 * 512];                  // [bt][dim512] sum(ek) partials
__device__ __half g_Mh[4 * 4 * 128 * 128];             // [b][chunk][o][hd128] hi
__device__ __half g_Ml[4 * 4 * 128 * 128];             // lo

extern __shared__ char smraw[];

// ---------------- PTX helpers ----------------
__device__ __forceinline__ uint32_t smem_u32(const void* p) {
    uint32_t a;
    asm("{ .reg .u64 t; cvta.to.shared.u64 t, %1; cvt.u32.u64 %0, t; }" : "=r"(a) : "l"(p));
    return a;
}
__device__ __forceinline__ void mma16816(float c[4], const uint32_t a[4],
                                         const uint32_t b[2]) {
    asm volatile(
        "mma.sync.aligned.m16n8k16.row.col.f32.f16.f16.f32 "
        "{%0,%1,%2,%3}, {%4,%5,%6,%7}, {%8,%9}, {%0,%1,%2,%3};"
        : "+f"(c[0]), "+f"(c[1]), "+f"(c[2]), "+f"(c[3])
        : "r"(a[0]), "r"(a[1]), "r"(a[2]), "r"(a[3]), "r"(b[0]), "r"(b[1]));
}
__device__ __forceinline__ void ldmx4(uint32_t r[4], uint32_t addr) {
    asm volatile("ldmatrix.sync.aligned.m8n8.x4.shared.b16 {%0,%1,%2,%3}, [%4];"
        : "=r"(r[0]), "=r"(r[1]), "=r"(r[2]), "=r"(r[3]) : "r"(addr));
}
// A 16x16 at (r0,k0): m0=rows r0..7@k0, m1=r0+8..15@k0, m2=r0..7@k8, m3=r0+8..15@k8
__device__ __forceinline__ uint32_t a_addr(uint32_t base, int r0, int k0) {
    const int l = threadIdx.x & 31;
    return base + ((r0 + (l & 15)) * ROWB + k0 + ((l >> 4) << 3)) * 2;
}
// B 16n x 16k at (n0,k0): m0=(n0..7,k0), m1=(n0..7,k8), m2=(n0+8..15,k0), m3=(n0+8..15,k8)
__device__ __forceinline__ uint32_t b_addr(uint32_t base, int n0, int k0) {
    const int l = threadIdx.x & 31;
    return base + ((n0 + (l & 7) + ((l >> 4) << 3)) * ROWB + k0 + (((l >> 3) & 1) << 3)) * 2;
}
// 32x32 warp-tile GEMM over K=128: A rows = wm.., B rows (n) = wn..
__device__ __forceinline__ void gemm32x32(float C[2][4][4], uint32_t A, uint32_t B,
                                          int wm, int wn) {
    #pragma unroll
    for (int k0 = 0; k0 < 128; k0 += 16) {
        uint32_t a0[4], a1[4], b0[4], b1[4];
        ldmx4(a0, a_addr(A, wm, k0));
        ldmx4(a1, a_addr(A, wm + 16, k0));
        ldmx4(b0, b_addr(B, wn, k0));
        ldmx4(b1, b_addr(B, wn + 16, k0));
        mma16816(C[0][0], a0, b0 + 0);  mma16816(C[0][1], a0, b0 + 2);
        mma16816(C[0][2], a0, b1 + 0);  mma16816(C[0][3], a0, b1 + 2);
        mma16816(C[1][0], a1, b0 + 0);  mma16816(C[1][1], a1, b0 + 2);
        mma16816(C[1][2], a1, b1 + 0);  mma16816(C[1][3], a1, b1 + 2);
    }
}
__device__ __forceinline__ void zeroC(float C[2][4][4]) {
    #pragma unroll
    for (int i = 0; i < 2; i++)
        #pragma unroll
        for (int j = 0; j < 4; j++)
            #pragma unroll
            for (int q = 0; q < 4; q++) C[i][j][q] = 0.f;
}

// ---------------- P1 ----------------
#define SMEM1 (5 * 128 * ROWB * 2 + 1024 * 4)

__global__ __launch_bounds__(512, 1) void attn_p1(
    const float* __restrict__ x,
    const float* __restrict__ Wk, const float* __restrict__ bk,
    const float* __restrict__ Wv, const float* __restrict__ bv)
{
    __half* xh  = (__half*)smraw;
    __half* xl  = xh + 128 * ROWB;
    __half* wh  = xl + 128 * ROWB;   // W hi; later vT hi
    __half* wl  = wh + 128 * ROWB;   // W lo; later vT lo
    __half* ekT = wl + 128 * ROWB;
    float* sb_bk = (float*)(ekT + 128 * ROWB);
    float* sb_bv = sb_bk + 512;

    const uint32_t uxh = smem_u32(xh), uxl = smem_u32(xl);
    const uint32_t uwh = smem_u32(wh), uwl = smem_u32(wl), uek = smem_u32(ekT);

    const int tid = threadIdx.x, w = tid >> 5, lane = tid & 31;
    const int tile = blockIdx.x, b = blockIdx.y;
    const int bt = b * 128 + tile;
    const float* xb = x + (size_t)b * 128 * 16384 + (size_t)tile * 128;

    for (int i = tid; i < 512; i += 512) { sb_bk[i] = bk[i]; sb_bv[i] = bv[i]; }

    // x tile -> fp16 hi/lo, layout [tok][ch]
    for (int idx = tid; idx < 16384; idx += 512) {
        int c = idx >> 7, t = idx & 127;
        float v = xb[(size_t)c * 16384 + t];
        __half h = __float2half_rn(v);
        xh[t * ROWB + c] = h;
        xl[t * ROWB + c] = __float2half_rn(v - __half2float(h));
    }
    __syncthreads();

    const int wm = (w >> 2) * 32;   // token block
    const int wn = (w & 3) * 32;    // dim block

    for (int p = 0; p < 4; p++) {
        // ---- Wk chunk (hi only) ----
        for (int idx = tid; idx < 16384; idx += 512)
            wh[(idx >> 7) * ROWB + (idx & 127)] = __float2half_rn(Wk[p * 16384 + idx]);
        __syncthreads();

        float C[2][4][4];
        zeroC(C);
        gemm32x32(C, uxh, uwh, wm, wn);
        __syncthreads();                 // all warps done reading wh

        // K epilogue: ek = exp(scale*(val+bk)) -> ekT[dim][tok]
        #pragma unroll
        for (int i = 0; i < 2; i++)
            #pragma unroll
            for (int j = 0; j < 4; j++) {
                int tok = wm + 16 * i + (lane >> 2);
                int dim = wn + 8 * j + ((lane & 3) << 1);
                float b0 = sb_bk[p * 128 + dim], b1 = sb_bk[p * 128 + dim + 1];
                ekT[dim * ROWB + tok]           = __float2half_rn(__expf(QSCALE * (C[i][j][0] + b0)));
                ekT[(dim + 1) * ROWB + tok]     = __float2half_rn(__expf(QSCALE * (C[i][j][1] + b1)));
                ekT[dim * ROWB + tok + 8]       = __float2half_rn(__expf(QSCALE * (C[i][j][2] + b0)));
                ekT[(dim + 1) * ROWB + tok + 8] = __float2half_rn(__expf(QSCALE * (C[i][j][3] + b1)));
            }
        __syncthreads();

        // per-dim sum of rounded ek (softmax-k denominator partial)
        if (tid < 128) {
            float s = 0.f;
            #pragma unroll 8
            for (int t = 0; t < 128; t++) s += __half2float(ekT[tid * ROWB + t]);
            g_spart[(size_t)bt * 512 + p * 128 + tid] = s;
        }

        // ---- Wv chunk hi/lo ----
        for (int idx = tid; idx < 16384; idx += 512) {
            float v = Wv[p * 16384 + idx];
            __half h = __float2half_rn(v);
            int o = (idx >> 7) * ROWB + (idx & 127);
            wh[o] = h;
            wl[o] = __float2half_rn(v - __half2float(h));
        }
        __syncthreads();

        zeroC(C);
        gemm32x32(C, uxh, uwh, wm, wn);   // x_hi * W_hi
        gemm32x32(C, uxh, uwl, wm, wn);   // x_hi * W_lo
        gemm32x32(C, uxl, uwh, wm, wn);   // x_lo * W_hi
        __syncthreads();                   // all warps done reading wh/wl

        // V epilogue: v+bv, split hi/lo -> vT (overlays wh/wl), [dim][tok]
        #pragma unroll
        for (int i = 0; i < 2; i++)
            #pragma unroll
            for (int j = 0; j < 4; j++) {
                int tok = wm + 16 * i + (lane >> 2);
                int dim = wn + 8 * j + ((lane & 3) << 1);
                float bv0 = sb_bv[p * 128 + dim], bv1 = sb_bv[p * 128 + dim + 1];
                float v0 = C[i][j][0] + bv0, v1 = C[i][j][1] + bv1;
                float v2 = C[i][j][2] + bv0, v3 = C[i][j][3] + bv1;
                __half h0 = __float2half_rn(v0), h1 = __float2half_rn(v1);
                __half h2 = __float2half_rn(v2), h3 = __float2half_rn(v3);
                wh[dim * ROWB + tok]           = h0;
                wh[(dim + 1) * ROWB + tok]     = h1;
                wh[dim * ROWB + tok + 8]       = h2;
                wh[(dim + 1) * ROWB + tok + 8] = h3;
                wl[dim * ROWB + tok]           = __float2half_rn(v0 - __half2float(h0));
                wl[(dim + 1) * ROWB + tok]     = __float2half_rn(v1 - __half2float(h1));
                wl[dim * ROWB + tok + 8]       = __float2half_rn(v2 - __half2float(h2));
                wl[(dim + 1) * ROWB + tok + 8] = __float2half_rn(v3 - __half2float(h3));
            }
        __syncthreads();

        // ---- ctx GEMM: per head, D[d][e] = sum_t ekT[d][t] * vT[e][t] ----
        {
            const int hl = w >> 3, ww = w & 7;           // head-local, warp-in-head
            const int r0 = hl * 64 + (ww >> 1) * 16;     // d rows (16)
            const int e0 = hl * 64 + (ww & 1) * 32;      // e rows (32)
            float Cc[4][4];
            #pragma unroll
            for (int j = 0; j < 4; j++)
                #pragma unroll
                for (int q = 0; q < 4; q++) Cc[j][q] = 0.f;
            #pragma unroll
            for (int pass = 0; pass < 2; pass++) {
                const uint32_t V = pass ? uwl : uwh;
                #pragma unroll
                for (int k0 = 0; k0 < 128; k0 += 16) {
                    uint32_t a[4], b0[4], b1[4];
                    ldmx4(a, a_addr(uek, r0, k0));
                    ldmx4(b0, b_addr(V, e0, k0));
                    ldmx4(b1, b_addr(V, e0 + 16, k0));
                    mma16816(Cc[0], a, b0 + 0);  mma16816(Cc[1], a, b0 + 2);
                    mma16816(Cc[2], a, b1 + 0);  mma16816(Cc[3], a, b1 + 2);
                }
            }
            float* dst = g_ctxp + ((size_t)bt * 8 + 2 * p + hl) * 4096;
            const int d0 = (ww >> 1) * 16 + (lane >> 2);
            const int eb = (ww & 1) * 32;
            #pragma unroll
            for (int j = 0; j < 4; j++) {
                int e = eb + 8 * j + ((lane & 3) << 1);
                *(float2*)(dst + d0 * 64 + e)       = make_float2(Cc[j][0], Cc[j][1]);
                *(float2*)(dst + (d0 + 8) * 64 + e) = make_float2(Cc[j][2], Cc[j][3]);
            }
        }
        __syncthreads();   // protect ekT / vT before next chunk reuses buffers
    }
}

// ---------------- P2: reduce + normalize + fold Wo ----------------
#define SMEM2 ((64 + 8192 + 64 * 65) * 4)

__global__ __launch_bounds__(256) void attn_p2(const float* __restrict__ Wo)
{
    float* rS    = (float*)smraw;        // [64]
    float* wo_s  = rS + 64;              // [o128][e64]
    float* ctx_s = wo_s + 8192;          // [d64][65]
    const int b = blockIdx.x >> 3, h = blockIdx.x & 7, tid = threadIdx.x;

    if (tid < 64) {
        float s = 0.f;
        for (int t = 0; t < 128; t++)
            s += g_spart[(size_t)(b * 128 + t) * 512 + h * 64 + tid];
        rS[tid] = 1.f / s;
    }
    for (int idx = tid; idx < 8192; idx += 256)
        wo_s[idx] = Wo[(idx >> 6) * 512 + h * 64 + (idx & 63)];
    __syncthreads();

    for (int idx = tid; idx < 4096; idx += 256) {
        int d = idx >> 6, e = idx & 63;
        const float* src = g_ctxp + (size_t)(b * 128) * 32768 + h * 4096 + idx;
        float s = 0.f;
        for (int t = 0; t < 128; t++) s += src[(size_t)t * 32768];
        ctx_s[d * 65 + e] = s * rS[d];
    }
    __syncthreads();

    const int p = h >> 1;
    const size_t mb = (size_t)(b * 4 + p) * 16384 + (h & 1) * 64;
    for (int idx = tid; idx < 8192; idx += 256) {
        int o = idx >> 6, d = idx & 63;
        float s = 0.f;
        #pragma unroll 8
        for (int e = 0; e < 64; e++)
            s = fmaf(wo_s[o * 64 + e], ctx_s[d * 65 + e], s);
        __half hi = __float2half_rn(s);
        g_Mh[mb + o * 128 + d] = hi;
        g_Ml[mb + o * 128 + d] = __float2half_rn(s - __half2float(hi));
    }
}

// ---------------- P3: q recompute + per-head softmax + M application ----------------
#define SMEM3 (5 * 128 * ROWB * 2 + (512 + 128) * 4)

__global__ __launch_bounds__(512, 1) void attn_p3(
    const float* __restrict__ x,
    const float* __restrict__ Wq, const float* __restrict__ bq,
    const float* __restrict__ bo, float* __restrict__ out)
{
    __half* xh   = (__half*)smraw;
    __half* wq   = xh + 128 * ROWB;
    __half* qs   = wq + 128 * ROWB;      // [tok][dim] fp16 (normalized in place)
    __half* Mh_s = qs + 128 * ROWB;      // [o][hd] fp16
    __half* Ml_s = Mh_s + 128 * ROWB;
    float* sb_bq = (float*)(Ml_s + 128 * ROWB);   // [512]
    float* sb_bo = sb_bq + 512;                    // [128]

    const uint32_t uxh = smem_u32(xh), uwq = smem_u32(wq), uqs = smem_u32(qs);
    const uint32_t umh = smem_u32(Mh_s), uml = smem_u32(Ml_s);

    const int tid = threadIdx.x, w = tid >> 5, lane = tid & 31;
    const int tile = blockIdx.x, b = blockIdx.y;
    const float* xb = x + (size_t)b * 128 * 16384 + (size_t)tile * 128;

    for (int i = tid; i < 512; i += 512) sb_bq[i] = bq[i];
    if (tid < 128) sb_bo[tid] = bo[tid];

    for (int idx = tid; idx < 16384; idx += 512) {
        int c = idx >> 7, t = idx & 127;
        xh[t * ROWB + c] = __float2half_rn(xb[(size_t)c * 16384 + t]);
    }
    __syncthreads();

    const int wm = (w >> 2) * 32;   // o / token block (proj: token; out: o)
    const int wn = (w & 3) * 32;
    float Co[2][4][4];
    zeroC(Co);

    for (int p = 0; p < 4; p++) {
        for (int idx = tid; idx < 16384; idx += 512)
            wq[(idx >> 7) * ROWB + (idx & 127)] = __float2half_rn(Wq[p * 16384 + idx]);
        __syncthreads();

        float Cq[2][4][4];
        zeroC(Cq);
        gemm32x32(Cq, uxh, uwq, wm, wn);

        // q epilogue: eq = exp(scale*(val+bq)) -> qs[tok][dim]
        #pragma unroll
        for (int i = 0; i < 2; i++)
            #pragma unroll
            for (int j = 0; j < 4; j++) {
                int tok = wm + 16 * i + (lane >> 2);
                int dim = wn + 8 * j + ((lane & 3) << 1);
                float b0 = sb_bq[p * 128 + dim], b1 = sb_bq[p * 128 + dim + 1];
                __half2 h01 = __floats2half2_rn(__expf(QSCALE * (Cq[i][j][0] + b0)),
                                                __expf(QSCALE * (Cq[i][j][1] + b1)));
                __half2 h23 = __floats2half2_rn(__expf(QSCALE * (Cq[i][j][2] + b0)),
                                                __expf(QSCALE * (Cq[i][j][3] + b1)));
                *(__half2*)(qs + tok * ROWB + dim)       = h01;
                *(__half2*)(qs + (tok + 8) * ROWB + dim) = h23;
            }
        __syncthreads();

        // PER-HEAD softmax-q normalization in place (heads 2p, 2p+1).
        if (tid < 256) {
            const int tok = tid >> 1, hh = (tid & 1) << 6;
            __half* row = qs + tok * ROWB + hh;
            float s = 0.f;
            #pragma unroll
            for (int d = 0; d < 64; d += 2) {
                __half2 v = *(__half2*)(row + d);
                s += __low2float(v) + __high2float(v);
            }
            const float r = 1.f / s;
            #pragma unroll
            for (int d = 0; d < 64; d += 2) {
                __half2 v = *(__half2*)(row + d);
                *(__half2*)(row + d) =
                    __floats2half2_rn(__low2float(v) * r, __high2float(v) * r);
            }
        }

        // load M chunk hi/lo
        {
            const uint32_t* gh = (const uint32_t*)(g_Mh + (size_t)(b * 4 + p) * 16384);
            const uint32_t* gl = (const uint32_t*)(g_Ml + (size_t)(b * 4 + p) * 16384);
            for (int idx = tid; idx < 8192; idx += 512) {
                int o = idx >> 6, k2 = (idx & 63) * 2;
                *(uint32_t*)(Mh_s + o * ROWB + k2) = gh[idx];
                *(uint32_t*)(Ml_s + o * ROWB + k2) = gl[idx];
            }
        }
        __syncthreads();

        // out GEMM: Co[o][t] += M[o][hd] * qn[t][hd]  (2-pass hi/lo)
        gemm32x32(Co, umh, uqs, wm, wn);
        gemm32x32(Co, uml, uqs, wm, wn);
        __syncthreads();
    }

    float* ob = out + (size_t)b * 128 * 16384 + (size_t)tile * 128;
    #pragma unroll
    for (int i = 0; i < 2; i++)
        #pragma unroll
        for (int j = 0; j < 4; j++) {
            int o = wm + 16 * i + (lane >> 2);
            int t = wn + 8 * j + ((lane & 3) << 1);
            float bo0 = sb_bo[o], bo8 = sb_bo[o + 8];
            *(float2*)(ob + (size_t)o * 16384 + t) =
                make_float2(Co[i][j][0] + bo0, Co[i][j][1] + bo0);
            *(float2*)(ob + (size_t)(o + 8) * 16384 + t) =
                make_float2(Co[i][j][2] + bo8, Co[i][j][3] + bo8);
        }
}

// ---------------------------------------------------------------------------
extern "C" void kernel_launch(void* const* d_in, const int* in_sizes, int n_in,
                              void* d_out, int out_size)
{
    const float* x  = (const float*)d_in[0];
    const float* Wq = (const float*)d_in[1];
    const float* bq = (const float*)d_in[2];
    const float* Wk = (const float*)d_in[3];
    const float* bk = (const float*)d_in[4];
    const float* Wv = (const float*)d_in[5];
    const float* bv = (const float*)d_in[6];
    const float* Wo = (const float*)d_in[7];
    const float* bo = (const float*)d_in[8];
    float* out = (float*)d_out;

    cudaFuncSetAttribute(attn_p1, cudaFuncAttributeMaxDynamicSharedMemorySize, SMEM1);
    cudaFuncSetAttribute(attn_p2, cudaFuncAttributeMaxDynamicSharedMemorySize, SMEM2);
    cudaFuncSetAttribute(attn_p3, cudaFuncAttributeMaxDynamicSharedMemorySize, SMEM3);

    attn_p1<<<dim3(128, 4), 512, SMEM1>>>(x, Wk, bk, Wv, bv);
    attn_p2<<<32, 256, SMEM2>>>(Wo);
    attn_p3<<<dim3(128, 4), 512, SMEM3>>>(x, Wq, bq, bo, out);
}

// round 7
// speedup vs baseline: 6.5733x; 1.5545x over previous
#include <cuda_runtime.h>
#include <cuda_fp16.h>
#include <cstdint>

// ImageLinearAttention via warp-level mma.sync (m16n8k16 f16->f32), ldmatrix
// fragment loads, 512-thread CTAs. B=4, C=128, n=16384, HEADS=8, KD=VD=64.
// Single-pass fp16 GEMMs everywhere: errors in v/ctx/M average out in the
// token/dim reductions (see round-6 analysis); only x/W rounding matters.
//
// P1: per (b,tile): k-proj -> exp -> ekT; v-proj -> vT; ctx partials + sum(ek).
// P2: reduce ctx over tiles, normalize by 1/S, fold Wo -> M (fp16).
// P3: recompute q -> exp -> per-(token,head) softmax normalize; out = M*qn^T + bo.

#define ROWB 136                      // halves per smem row (128 + 8 pad)
#define QSCALE 0.35355339059327373f   // 64^-0.25

__device__ float  g_ctxp[(size_t)512 * 8 * 64 * 64];  // [bt][head][d][e] partials
__device__ float  g_spart[512 * 512];                  // [bt][dim512] sum(ek) partials
__device__ __half g_Mh[4 * 4 * 128 * 128];             // [b][chunk][o][hd128]

extern __shared__ char smraw[];

// ---------------- PTX helpers ----------------
__device__ __forceinline__ uint32_t smem_u32(const void* p) {
    uint32_t a;
    asm("{ .reg .u64 t; cvta.to.shared.u64 t, %1; cvt.u32.u64 %0, t; }" : "=r"(a) : "l"(p));
    return a;
}
__device__ __forceinline__ void mma16816(float c[4], const uint32_t a[4],
                                         const uint32_t b[2]) {
    asm volatile(
        "mma.sync.aligned.m16n8k16.row.col.f32.f16.f16.f32 "
        "{%0,%1,%2,%3}, {%4,%5,%6,%7}, {%8,%9}, {%0,%1,%2,%3};"
        : "+f"(c[0]), "+f"(c[1]), "+f"(c[2]), "+f"(c[3])
        : "r"(a[0]), "r"(a[1]), "r"(a[2]), "r"(a[3]), "r"(b[0]), "r"(b[1]));
}
__device__ __forceinline__ void ldmx4(uint32_t r[4], uint32_t addr) {
    asm volatile("ldmatrix.sync.aligned.m8n8.x4.shared.b16 {%0,%1,%2,%3}, [%4];"
        : "=r"(r[0]), "=r"(r[1]), "=r"(r[2]), "=r"(r[3]) : "r"(addr));
}
// A 16x16 at (r0,k0): m0=rows r0..7@k0, m1=r0+8..15@k0, m2=r0..7@k8, m3=r0+8..15@k8
__device__ __forceinline__ uint32_t a_addr(uint32_t base, int r0, int k0) {
    const int l = threadIdx.x & 31;
    return base + ((r0 + (l & 15)) * ROWB + k0 + ((l >> 4) << 3)) * 2;
}
// B 16n x 16k at (n0,k0): m0=(n0..7,k0), m1=(n0..7,k8), m2=(n0+8..15,k0), m3=(n0+8..15,k8)
__device__ __forceinline__ uint32_t b_addr(uint32_t base, int n0, int k0) {
    const int l = threadIdx.x & 31;
    return base + ((n0 + (l & 7) + ((l >> 4) << 3)) * ROWB + k0 + (((l >> 3) & 1) << 3)) * 2;
}
// 32x32 warp-tile GEMM over K=128: A rows = wm.., B rows (n) = wn..
__device__ __forceinline__ void gemm32x32(float C[2][4][4], uint32_t A, uint32_t B,
                                          int wm, int wn) {
    #pragma unroll
    for (int k0 = 0; k0 < 128; k0 += 16) {
        uint32_t a0[4], a1[4], b0[4], b1[4];
        ldmx4(a0, a_addr(A, wm, k0));
        ldmx4(a1, a_addr(A, wm + 16, k0));
        ldmx4(b0, b_addr(B, wn, k0));
        ldmx4(b1, b_addr(B, wn + 16, k0));
        mma16816(C[0][0], a0, b0 + 0);  mma16816(C[0][1], a0, b0 + 2);
        mma16816(C[0][2], a0, b1 + 0);  mma16816(C[0][3], a0, b1 + 2);
        mma16816(C[1][0], a1, b0 + 0);  mma16816(C[1][1], a1, b0 + 2);
        mma16816(C[1][2], a1, b1 + 0);  mma16816(C[1][3], a1, b1 + 2);
    }
}
__device__ __forceinline__ void zeroC(float C[2][4][4]) {
    #pragma unroll
    for (int i = 0; i < 2; i++)
        #pragma unroll
        for (int j = 0; j < 4; j++)
            #pragma unroll
            for (int q = 0; q < 4; q++) C[i][j][q] = 0.f;
}
// float4 gmem row -> fp16 smem row (row-major, k contiguous)
__device__ __forceinline__ void loadW16(const float* __restrict__ W, __half* dst, int tid) {
    const float4* W4 = (const float4*)W;
    #pragma unroll
    for (int idx = tid; idx < 4096; idx += 512) {
        float4 v = W4[idx];
        __half* d = dst + (idx >> 5) * ROWB + ((idx & 31) << 2);
        *(__half2*)d       = __floats2half2_rn(v.x, v.y);
        *(__half2*)(d + 2) = __floats2half2_rn(v.z, v.w);
    }
}

// ---------------- P1 ----------------
#define SMEM1 (3 * 128 * ROWB * 2 + 1024 * 4)

__global__ __launch_bounds__(512, 1) void attn_p1(
    const float* __restrict__ x,
    const float* __restrict__ Wk, const float* __restrict__ bk,
    const float* __restrict__ Wv, const float* __restrict__ bv)
{
    __half* xh  = (__half*)smraw;
    __half* wh  = xh + 128 * ROWB;   // W; later vT overlay
    __half* ekT = wh + 128 * ROWB;
    float* sb_bk = (float*)(ekT + 128 * ROWB);
    float* sb_bv = sb_bk + 512;

    const uint32_t uxh = smem_u32(xh), uwh = smem_u32(wh), uek = smem_u32(ekT);

    const int tid = threadIdx.x, w = tid >> 5, lane = tid & 31;
    const int tile = blockIdx.x, b = blockIdx.y;
    const int bt = b * 128 + tile;
    const float* xb = x + (size_t)b * 128 * 16384 + (size_t)tile * 128;

    if (tid < 512) { sb_bk[tid] = bk[tid]; sb_bv[tid] = bv[tid]; }

    // x tile -> fp16, layout [tok][ch] (transposed store)
    #pragma unroll
    for (int idx = tid; idx < 4096; idx += 512) {
        int c = idx >> 5, t = (idx & 31) << 2;
        float4 v = *(const float4*)(xb + (size_t)c * 16384 + t);
        xh[t * ROWB + c]       = __float2half_rn(v.x);
        xh[(t + 1) * ROWB + c] = __float2half_rn(v.y);
        xh[(t + 2) * ROWB + c] = __float2half_rn(v.z);
        xh[(t + 3) * ROWB + c] = __float2half_rn(v.w);
    }
    __syncthreads();

    const int wm = (w >> 2) * 32;   // token block
    const int wn = (w & 3) * 32;    // dim block

    for (int p = 0; p < 4; p++) {
        // ---- K chunk ----
        loadW16(Wk + p * 16384, wh, tid);
        __syncthreads();

        float C[2][4][4];
        zeroC(C);
        gemm32x32(C, uxh, uwh, wm, wn);
        __syncthreads();                 // all warps done reading wh

        // K epilogue: ek = exp(scale*(val+bk)) -> ekT[dim][tok]; Wv load into wh
        #pragma unroll
        for (int i = 0; i < 2; i++)
            #pragma unroll
            for (int j = 0; j < 4; j++) {
                int tok = wm + 16 * i + (lane >> 2);
                int dim = wn + 8 * j + ((lane & 3) << 1);
                float b0 = sb_bk[p * 128 + dim], b1 = sb_bk[p * 128 + dim + 1];
                ekT[dim * ROWB + tok]           = __float2half_rn(__expf(QSCALE * (C[i][j][0] + b0)));
                ekT[(dim + 1) * ROWB + tok]     = __float2half_rn(__expf(QSCALE * (C[i][j][1] + b1)));
                ekT[dim * ROWB + tok + 8]       = __float2half_rn(__expf(QSCALE * (C[i][j][2] + b0)));
                ekT[(dim + 1) * ROWB + tok + 8] = __float2half_rn(__expf(QSCALE * (C[i][j][3] + b1)));
            }
        loadW16(Wv + p * 16384, wh, tid);
        __syncthreads();

        // per-dim sum of rounded ek (softmax-k denominator partial)
        if (tid < 128) {
            float s = 0.f;
            #pragma unroll 8
            for (int t = 0; t < 128; t++) s += __half2float(ekT[tid * ROWB + t]);
            g_spart[(size_t)bt * 512 + p * 128 + tid] = s;
        }

        // ---- V chunk ----
        zeroC(C);
        gemm32x32(C, uxh, uwh, wm, wn);
        __syncthreads();                 // all warps done reading wh (Wv)

        // V epilogue: v+bv -> vT (overlays wh), [dim][tok]
        #pragma unroll
        for (int i = 0; i < 2; i++)
            #pragma unroll
            for (int j = 0; j < 4; j++) {
                int tok = wm + 16 * i + (lane >> 2);
                int dim = wn + 8 * j + ((lane & 3) << 1);
                float bv0 = sb_bv[p * 128 + dim], bv1 = sb_bv[p * 128 + dim + 1];
                wh[dim * ROWB + tok]           = __float2half_rn(C[i][j][0] + bv0);
                wh[(dim + 1) * ROWB + tok]     = __float2half_rn(C[i][j][1] + bv1);
                wh[dim * ROWB + tok + 8]       = __float2half_rn(C[i][j][2] + bv0);
                wh[(dim + 1) * ROWB + tok + 8] = __float2half_rn(C[i][j][3] + bv1);
            }
        __syncthreads();

        // ---- ctx GEMM: per head, D[d][e] = sum_t ekT[d][t] * vT[e][t] ----
        {
            const int hl = w >> 3, ww = w & 7;           // head-local, warp-in-head
            const int r0 = hl * 64 + (ww >> 1) * 16;     // d rows (16)
            const int e0 = hl * 64 + (ww & 1) * 32;      // e rows (32)
            float Cc[4][4];
            #pragma unroll
            for (int j = 0; j < 4; j++)
                #pragma unroll
                for (int q = 0; q < 4; q++) Cc[j][q] = 0.f;
            #pragma unroll
            for (int k0 = 0; k0 < 128; k0 += 16) {
                uint32_t a[4], b0[4], b1[4];
                ldmx4(a, a_addr(uek, r0, k0));
                ldmx4(b0, b_addr(uwh, e0, k0));
                ldmx4(b1, b_addr(uwh, e0 + 16, k0));
                mma16816(Cc[0], a, b0 + 0);  mma16816(Cc[1], a, b0 + 2);
                mma16816(Cc[2], a, b1 + 0);  mma16816(Cc[3], a, b1 + 2);
            }
            float* dst = g_ctxp + ((size_t)bt * 8 + 2 * p + hl) * 4096;
            const int d0 = (ww >> 1) * 16 + (lane >> 2);
            const int eb = (ww & 1) * 32;
            #pragma unroll
            for (int j = 0; j < 4; j++) {
                int e = eb + 8 * j + ((lane & 3) << 1);
                *(float2*)(dst + d0 * 64 + e)       = make_float2(Cc[j][0], Cc[j][1]);
                *(float2*)(dst + (d0 + 8) * 64 + e) = make_float2(Cc[j][2], Cc[j][3]);
            }
        }
        __syncthreads();   // protect ekT / vT before next chunk reuses buffers
    }
}

// ---------------- P2: reduce + normalize + fold Wo ----------------
#define SMEM2 ((64 + 8192 + 64 * 65) * 4)

__global__ __launch_bounds__(256) void attn_p2(const float* __restrict__ Wo)
{
    float* rS    = (float*)smraw;        // [64]
    float* wo_s  = rS + 64;              // [o128][e64]
    float* ctx_s = wo_s + 8192;          // [d64][65]
    const int b = blockIdx.x >> 3, h = blockIdx.x & 7, tid = threadIdx.x;

    if (tid < 64) {
        float s = 0.f;
        for (int t = 0; t < 128; t++)
            s += g_spart[(size_t)(b * 128 + t) * 512 + h * 64 + tid];
        rS[tid] = 1.f / s;
    }
    for (int idx = tid; idx < 8192; idx += 256)
        wo_s[idx] = Wo[(idx >> 6) * 512 + h * 64 + (idx & 63)];
    __syncthreads();

    for (int idx = tid; idx < 4096; idx += 256) {
        int d = idx >> 6, e = idx & 63;
        const float* src = g_ctxp + (size_t)(b * 128) * 32768 + h * 4096 + idx;
        float s = 0.f;
        for (int t = 0; t < 128; t++) s += src[(size_t)t * 32768];
        ctx_s[d * 65 + e] = s * rS[d];
    }
    __syncthreads();

    const int p = h >> 1;
    const size_t mb = (size_t)(b * 4 + p) * 16384 + (h & 1) * 64;
    for (int idx = tid; idx < 8192; idx += 256) {
        int o = idx >> 6, d = idx & 63;
        float s = 0.f;
        #pragma unroll 8
        for (int e = 0; e < 64; e++)
            s = fmaf(wo_s[o * 64 + e], ctx_s[d * 65 + e], s);
        g_Mh[mb + o * 128 + d] = __float2half_rn(s);
    }
}

// ---------------- P3: q recompute + per-head softmax + M application ----------------
#define SMEM3 (3 * 128 * ROWB * 2 + (512 + 128) * 4)

__global__ __launch_bounds__(512, 1) void attn_p3(
    const float* __restrict__ x,
    const float* __restrict__ Wq, const float* __restrict__ bq,
    const float* __restrict__ bo, float* __restrict__ out)
{
    __half* xh = (__half*)smraw;
    __half* wq = xh + 128 * ROWB;        // Wq; later M overlay
    __half* qs = wq + 128 * ROWB;        // [tok][dim] fp16 (normalized in place)
    float* sb_bq = (float*)(qs + 128 * ROWB);   // [512]
    float* sb_bo = sb_bq + 512;                  // [128]

    const uint32_t uxh = smem_u32(xh), uwq = smem_u32(wq), uqs = smem_u32(qs);

    const int tid = threadIdx.x, w = tid >> 5, lane = tid & 31;
    const int tile = blockIdx.x, b = blockIdx.y;
    const float* xb = x + (size_t)b * 128 * 16384 + (size_t)tile * 128;

    if (tid < 512) sb_bq[tid] = bq[tid];
    if (tid < 128) sb_bo[tid] = bo[tid];

    #pragma unroll
    for (int idx = tid; idx < 4096; idx += 512) {
        int c = idx >> 5, t = (idx & 31) << 2;
        float4 v = *(const float4*)(xb + (size_t)c * 16384 + t);
        xh[t * ROWB + c]       = __float2half_rn(v.x);
        xh[(t + 1) * ROWB + c] = __float2half_rn(v.y);
        xh[(t + 2) * ROWB + c] = __float2half_rn(v.z);
        xh[(t + 3) * ROWB + c] = __float2half_rn(v.w);
    }
    __syncthreads();

    const int wm = (w >> 2) * 32;   // token block (proj) / o block (out)
    const int wn = (w & 3) * 32;
    float Co[2][4][4];
    zeroC(Co);

    for (int p = 0; p < 4; p++) {
        loadW16(Wq + p * 16384, wq, tid);
        __syncthreads();

        float Cq[2][4][4];
        zeroC(Cq);
        gemm32x32(Cq, uxh, uwq, wm, wn);
        __syncthreads();                 // all warps done reading wq

        // q epilogue: eq = exp(scale*(val+bq)) -> qs[tok][dim]; M load into wq
        #pragma unroll
        for (int i = 0; i < 2; i++)
            #pragma unroll
            for (int j = 0; j < 4; j++) {
                int tok = wm + 16 * i + (lane >> 2);
                int dim = wn + 8 * j + ((lane & 3) << 1);
                float b0 = sb_bq[p * 128 + dim], b1 = sb_bq[p * 128 + dim + 1];
                __half2 h01 = __floats2half2_rn(__expf(QSCALE * (Cq[i][j][0] + b0)),
                                                __expf(QSCALE * (Cq[i][j][1] + b1)));
                __half2 h23 = __floats2half2_rn(__expf(QSCALE * (Cq[i][j][2] + b0)),
                                                __expf(QSCALE * (Cq[i][j][3] + b1)));
                *(__half2*)(qs + tok * ROWB + dim)       = h01;
                *(__half2*)(qs + (tok + 8) * ROWB + dim) = h23;
            }
        {
            const uint32_t* gh = (const uint32_t*)(g_Mh + (size_t)(b * 4 + p) * 16384);
            #pragma unroll
            for (int idx = tid; idx < 8192; idx += 512) {
                int o = idx >> 6, k2 = (idx & 63) * 2;
                *(uint32_t*)(wq + o * ROWB + k2) = gh[idx];
            }
        }
        __syncthreads();

        // PER-HEAD softmax-q normalization in place (heads 2p, 2p+1).
        if (tid < 256) {
            const int tok = tid >> 1, hh = (tid & 1) << 6;
            __half* row = qs + tok * ROWB + hh;
            float s = 0.f;
            #pragma unroll
            for (int d = 0; d < 64; d += 2) {
                __half2 v = *(__half2*)(row + d);
                s += __low2float(v) + __high2float(v);
            }
            const float r = 1.f / s;
            #pragma unroll
            for (int d = 0; d < 64; d += 2) {
                __half2 v = *(__half2*)(row + d);
                *(__half2*)(row + d) =
                    __floats2half2_rn(__low2float(v) * r, __high2float(v) * r);
            }
        }
        __syncthreads();

        // out GEMM: Co[o][t] += M[o][hd] * qn[t][hd]
        gemm32x32(Co, uwq, uqs, wm, wn);
        __syncthreads();
    }

    float* ob = out + (size_t)b * 128 * 16384 + (size_t)tile * 128;
    #pragma unroll
    for (int i = 0; i < 2; i++)
        #pragma unroll
        for (int j = 0; j < 4; j++) {
            int o = wm + 16 * i + (lane >> 2);
            int t = wn + 8 * j + ((lane & 3) << 1);
            float bo0 = sb_bo[o], bo8 = sb_bo[o + 8];
            *(float2*)(ob + (size_t)o * 16384 + t) =
                make_float2(Co[i][j][0] + bo0, Co[i][j][1] + bo0);
            *(float2*)(ob + (size_t)(o + 8) * 16384 + t) =
                make_float2(Co[i][j][2] + bo8, Co[i][j][3] + bo8);
        }
}

// ---------------------------------------------------------------------------
extern "C" void kernel_launch(void* const* d_in, const int* in_sizes, int n_in,
                              void* d_out, int out_size)
{
    const float* x  = (const float*)d_in[0];
    const float* Wq = (const float*)d_in[1];
    const float* bq = (const float*)d_in[2];
    const float* Wk = (const float*)d_in[3];
    const float* bk = (const float*)d_in[4];
    const float* Wv = (const float*)d_in[5];
    const float* bv = (const float*)d_in[6];
    const float* Wo = (const float*)d_in[7];
    const float* bo = (const float*)d_in[8];
    float* out = (float*)d_out;

    cudaFuncSetAttribute(attn_p1, cudaFuncAttributeMaxDynamicSharedMemorySize, SMEM1);
    cudaFuncSetAttribute(attn_p2, cudaFuncAttributeMaxDynamicSharedMemorySize, SMEM2);
    cudaFuncSetAttribute(attn_p3, cudaFuncAttributeMaxDynamicSharedMemorySize, SMEM3);

    attn_p1<<<dim3(128, 4), 512, SMEM1>>>(x, Wk, bk, Wv, bv);
    attn_p2<<<32, 256, SMEM2>>>(Wo);
    attn_p3<<<dim3(128, 4), 512, SMEM3>>>(x, Wq, bq, bo, out);
}